// round 13
// baseline (speedup 1.0000x reference)
#include <cuda_runtime.h>
#include <cuda_bf16.h>
#include <math.h>
#include <cstdint>

// Problem constants
#define BB   4
#define LL   2048
#define EE   7
#define DD   512
#define HH   8
#define DHH  64
#define PP   720
#define NLL  2
#define UU   40
#define BL   (BB*LL)          // 8192 rows
#define SCALE 0.125f          // 1/sqrt(64)
#define ASPLIT 8
#define ATILES (16/ASPLIT)    // key tiles of 128 per split block

// ---------------- scratch (device globals; no allocation allowed) ----------
__device__ float g_h[BL*DD];
__device__ float g_q[BL*DD];
__device__ float g_k[BL*DD];
__device__ float g_v[BL*DD];
__device__ __nv_bfloat16 g_qh[BL*DD];
__device__ __nv_bfloat16 g_kh[BL*DD];
__device__ float g_ctx[BL*DD];
__device__ float g_t1[BL*DD];
__device__ float g_t2[BL*DD];
__device__ float g_M[BB*HH*LL];
__device__ int   g_topk[BB*HH*UU];
__device__ float g_cval[BB*HH*8*UU];        // per-chunk topk candidates
__device__ int   g_cidx[BB*HH*8*UU];
__device__ float g_wt[12*DD*DD];            // transposed weights, [n][k], tf32-rounded
__device__ float g_pacc[32*ASPLIT*UU*DHH];  // split-KV partial outputs
__device__ float g_pm[32*ASPLIT*UU];
__device__ float g_pl[32*ASPLIT*UU];
__device__ float g_pvs[32*ASPLIT*DHH];      // partial V column sums

// ---------------- helpers ---------------------------------------------------
__device__ __forceinline__ float totf32(float x) {
    uint32_t r;
    asm("cvt.rna.tf32.f32 %0, %1;" : "=r"(r) : "f"(x));
    return __uint_as_float(r);
}
__device__ __forceinline__ void mma_tf32(float c[4], const uint32_t a[4], const uint32_t b[2]) {
    asm volatile("mma.sync.aligned.m16n8k8.row.col.f32.tf32.tf32.f32 "
        "{%0,%1,%2,%3}, {%4,%5,%6,%7}, {%8,%9}, {%0,%1,%2,%3};"
        : "+f"(c[0]), "+f"(c[1]), "+f"(c[2]), "+f"(c[3])
        : "r"(a[0]), "r"(a[1]), "r"(a[2]), "r"(a[3]), "r"(b[0]), "r"(b[1]));
}
__device__ __forceinline__ void mma_bf16(float c[4], const uint32_t a[4], const uint32_t b[2]) {
    asm volatile("mma.sync.aligned.m16n8k16.row.col.f32.bf16.bf16.f32 "
        "{%0,%1,%2,%3}, {%4,%5,%6,%7}, {%8,%9}, {%0,%1,%2,%3};"
        : "+f"(c[0]), "+f"(c[1]), "+f"(c[2]), "+f"(c[3])
        : "r"(a[0]), "r"(a[1]), "r"(a[2]), "r"(a[3]), "r"(b[0]), "r"(b[1]));
}
__device__ __forceinline__ void ldmA(uint32_t r[4], uint32_t addr) {
    asm volatile("ldmatrix.sync.aligned.m8n8.x4.shared.b16 {%0,%1,%2,%3}, [%4];"
        : "=r"(r[0]), "=r"(r[1]), "=r"(r[2]), "=r"(r[3]) : "r"(addr));
}
__device__ __forceinline__ uint32_t smem_u32(const void* p) {
    uint32_t a;
    asm("{ .reg .u64 t; cvta.to.shared.u64 t, %1; cvt.u32.u64 %0, t; }" : "=r"(a) : "l"(p));
    return a;
}
__device__ __forceinline__ void cp_async16(uint32_t s, const void* g) {
    asm volatile("cp.async.cg.shared.global [%0], [%1], 16;" :: "r"(s), "l"(g));
}
#define CP_COMMIT() asm volatile("cp.async.commit_group;" ::: "memory")
#define CP_WAIT(n)  asm volatile("cp.async.wait_group %0;" :: "n"(n) : "memory")

// ---------------- batched weight transpose: Wt[n][k] = tf32(W[k][n]) -------
__global__ void transpose_all(const float* __restrict__ Wq, const float* __restrict__ Wk,
                              const float* __restrict__ Wv, const float* __restrict__ Wo,
                              const float* __restrict__ W1, const float* __restrict__ W2) {
    __shared__ float tile[32][33];
    int z = blockIdx.z;
    int lay = z / 6, j = z % 6;
    const float* W = (j==0?Wq : j==1?Wk : j==2?Wv : j==3?Wo : j==4?W1 : W2)
                     + (size_t)lay*DD*DD;
    float* Wt = g_wt + (size_t)z*DD*DD;
    int x0 = blockIdx.x*32, y0 = blockIdx.y*32;
    int tx = threadIdx.x, ty = threadIdx.y;   // (32,8)
#pragma unroll
    for (int jj = 0; jj < 32; jj += 8)
        tile[ty+jj][tx] = W[(size_t)(y0+ty+jj)*DD + x0+tx];
    __syncthreads();
#pragma unroll
    for (int jj = 0; jj < 32; jj += 8)
        Wt[(size_t)(x0+ty+jj)*DD + y0+tx] = totf32(tile[tx][ty+jj]);
}

// ---------------- embedding: h = x @ emb_w + emb_b -------------------------
__global__ void embed_kernel(const float* __restrict__ x,
                             const float* __restrict__ w,
                             const float* __restrict__ b) {
    int row = blockIdx.x;
    int d   = blockIdx.y * 256 + threadIdx.x;
    __shared__ float xs[EE];
    if (threadIdx.x < EE) xs[threadIdx.x] = x[row*EE + threadIdx.x];
    __syncthreads();
    float acc = b[d];
#pragma unroll
    for (int e = 0; e < EE; e++) acc += xs[e] * w[e*DD + d];
    g_h[(size_t)row*DD + d] = acc;
}

// =============== tf32 mma.sync GEMM (cp.async 3-stage) =====================
// CTA tile 256m x 128n, 8 warps in 4m x 2n of 64x64 tiles (LDS:MMA = 1.0).
#define GPAD 36
#define ABUF (256*GPAD)              // 9216 floats
#define BBUF (128*GPAD)              // 4608 floats
#define GSTAGE 3
__device__ __forceinline__ void gemm_body(const float* __restrict__ A,
                                          const float* __restrict__ Bt,
                                          const float* __restrict__ bias,
                                          float* __restrict__ C, int relu,
                                          __nv_bfloat16* __restrict__ bfout,
                                          float* sm) {
    int t = threadIdx.x, l = t & 31, w = t >> 5;
    int g = l >> 2, tig = l & 3;
    int wm = w >> 1, wn = w & 1;              // 4m x 2n
    int m0 = blockIdx.y * 256, n0 = blockIdx.x * 128;

    const float* Ab = A  + (size_t)m0 * DD;
    const float* Bb = Bt + (size_t)n0 * DD;

    uint32_t sA = smem_u32(sm);
    uint32_t sB = sA + GSTAGE*ABUF*4;

    int irow = t >> 3;            // 0..31
    int ic = (t & 7) * 4;
#define GEMM_ISSUE(chunk, stage) do {                                          \
        int _k0 = (chunk) * 32;                                                \
        uint32_t _oa = sA + (uint32_t)(stage)*ABUF*4;                          \
        uint32_t _ob = sB + (uint32_t)(stage)*BBUF*4;                          \
        _Pragma("unroll")                                                      \
        for (int _r = 0; _r < 8; _r++) {                                       \
            int _row = _r*32 + irow;                                           \
            cp_async16(_oa + (uint32_t)(_row*GPAD + ic)*4,                     \
                       Ab + (size_t)_row*DD + _k0 + ic);                       \
        }                                                                      \
        _Pragma("unroll")                                                      \
        for (int _r = 0; _r < 4; _r++) {                                       \
            int _row = _r*32 + irow;                                           \
            cp_async16(_ob + (uint32_t)(_row*GPAD + ic)*4,                     \
                       Bb + (size_t)_row*DD + _k0 + ic);                       \
        }                                                                      \
        CP_COMMIT();                                                           \
    } while (0)

    float c[4][8][4];
#pragma unroll
    for (int i = 0; i < 4; i++)
#pragma unroll
        for (int j = 0; j < 8; j++)
#pragma unroll
            for (int r = 0; r < 4; r++) c[i][j][r] = 0.f;

    GEMM_ISSUE(0, 0);
    GEMM_ISSUE(1, 1);

    for (int chunk = 0; chunk < 16; chunk++) {
        if (chunk < 15) { CP_WAIT(1); } else { CP_WAIT(0); }
        __syncthreads();
        if (chunk + 2 < 16) GEMM_ISSUE(chunk + 2, (chunk + 2) % GSTAGE);

        const float* Ap = sm + (chunk % GSTAGE)*ABUF;
        const float* Bp = sm + GSTAGE*ABUF + (chunk % GSTAGE)*BBUF;
#pragma unroll
        for (int kk = 0; kk < 4; kk++) {
            int kb = kk * 8;
            uint32_t af[4][4];
#pragma unroll
            for (int mt = 0; mt < 4; mt++) {
                int base = (wm*64 + mt*16 + g)*GPAD + kb + tig;
                af[mt][0] = __float_as_uint(Ap[base]);
                af[mt][1] = __float_as_uint(Ap[base + 8*GPAD]);
                af[mt][2] = __float_as_uint(Ap[base + 4]);
                af[mt][3] = __float_as_uint(Ap[base + 8*GPAD + 4]);
            }
            uint32_t bf[8][2];
#pragma unroll
            for (int nt = 0; nt < 8; nt++) {
                int base = (wn*64 + nt*8 + g)*GPAD + kb + tig;
                bf[nt][0] = __float_as_uint(Bp[base]);
                bf[nt][1] = __float_as_uint(Bp[base + 4]);
            }
#pragma unroll
            for (int mt = 0; mt < 4; mt++)
#pragma unroll
                for (int nt = 0; nt < 8; nt++)
                    mma_tf32(c[mt][nt], af[mt], bf[nt]);
        }
        __syncthreads();
    }

#pragma unroll
    for (int mt = 0; mt < 4; mt++) {
        int row = m0 + wm*64 + mt*16 + g;
#pragma unroll
        for (int nt = 0; nt < 8; nt++) {
            int col = n0 + wn*64 + nt*8 + 2*tig;
            float b0 = bias[col], b1 = bias[col+1];
            float2 v0 = make_float2(c[mt][nt][0] + b0, c[mt][nt][1] + b1);
            float2 v1 = make_float2(c[mt][nt][2] + b0, c[mt][nt][3] + b1);
            if (relu) {
                v0.x = fmaxf(v0.x, 0.f); v0.y = fmaxf(v0.y, 0.f);
                v1.x = fmaxf(v1.x, 0.f); v1.y = fmaxf(v1.y, 0.f);
            }
            *(float2*)(C + (size_t)row*DD + col)     = v0;
            *(float2*)(C + (size_t)(row+8)*DD + col) = v1;
            if (bfout) {
                __nv_bfloat162 p0 = __float22bfloat162_rn(v0);
                __nv_bfloat162 p1 = __float22bfloat162_rn(v1);
                *(__nv_bfloat162*)(bfout + (size_t)row*DD + col)     = p0;
                *(__nv_bfloat162*)(bfout + (size_t)(row+8)*DD + col) = p1;
            }
        }
    }
#undef GEMM_ISSUE
}

__global__ void __launch_bounds__(256) gemm_mma(const float* __restrict__ A,
                                                const float* __restrict__ Bt,
                                                const float* __restrict__ bias,
                                                float* __restrict__ C, int relu) {
    extern __shared__ float sm[];
    gemm_body(A, Bt, bias, C, relu, nullptr, sm);
}

__global__ void __launch_bounds__(256) gemm_qkv(int lay,
                                                const float* __restrict__ bq,
                                                const float* __restrict__ bk,
                                                const float* __restrict__ bv) {
    extern __shared__ float sm[];
    int z = blockIdx.z;
    const float* Bt = g_wt + (size_t)(lay*6 + z)*DD*DD;
    const float* bias = (z==0) ? bq : (z==1) ? bk : bv;
    float* C = (z==0) ? g_q : (z==1) ? g_k : g_v;
    __nv_bfloat16* bfout = (z==0) ? g_qh : (z==1) ? g_kh : nullptr;
    gemm_body(g_h, Bt, bias, C, 0, bfout, sm);
}

// ========= score stats: M = SCALE*(max - mean), bf16 m16n8k16 ==============
// CTA tile 256 q x 128 k warp layout; K streamed in stages of 256 rows.
// A fragments via ldmatrix.x4 (1 instr replaces 16 LDS).
#define HPADW 36                     // row pad in 32-bit words (72 halves)
#define QHB (256*72*2)               // Q tile bytes (36864); also = one K stage
__global__ void __launch_bounds__(256) mstats_mma() {
    extern __shared__ float sm[];
    float* redm = (float*)((char*)sm + 3*QHB);   // [2][256]
    float* reds = redm + 512;

    int t = threadIdx.x, w = t >> 5, l = t & 31;
    int g = l >> 2, tig = l & 3;
    int wm = w >> 1, wn = w & 1;              // 4m x 2n
    int bh = blockIdx.y, b = bh >> 3, h = bh & 7;
    int q0 = blockIdx.x * 256;

    const __nv_bfloat16* qb = g_qh + (size_t)b*LL*DD + h*DHH;
    const __nv_bfloat16* kb = g_kh + (size_t)b*LL*DD + h*DHH;

    uint32_t sQ = smem_u32(sm);
    uint32_t sK = sQ + QHB;

    // per-lane ldmatrix base: row = wm*64 + (l&15), col-half = (l>>4)*16 bytes
    uint32_t lmBase = sQ + (uint32_t)((wm*64 + (l & 15))*144 + (l >> 4)*16);

    int lrow = t >> 3;            // 0..31
    int lc8  = t & 7;             // 16B chunk within 128B row

#define MST_ISSUE(st, stage) do {                                              \
        int _n0 = (st) * 256;                                                  \
        uint32_t _ok = sK + (uint32_t)(stage)*QHB;                             \
        _Pragma("unroll")                                                      \
        for (int _r = 0; _r < 8; _r++) {                                       \
            int _row = _r*32 + lrow;                                           \
            cp_async16(_ok + (uint32_t)(_row*144 + lc8*16),                    \
                       kb + (size_t)(_n0 + _row)*DD + lc8*8);                  \
        }                                                                      \
        CP_COMMIT();                                                           \
    } while (0)

    // Q tile [256][64] bf16 resident
#pragma unroll
    for (int r = 0; r < 8; r++) {
        int row = r*32 + lrow;
        *(uint4*)((char*)sm + row*144 + lc8*16) =
            *(const uint4*)(qb + (size_t)(q0 + row)*DD + lc8*8);
    }

    MST_ISSUE(0, 0);

    float mx[8], sum[8];
#pragma unroll
    for (int s = 0; s < 8; s++) { mx[s] = -INFINITY; sum[s] = 0.f; }

    for (int st = 0; st < 8; st++) {
        if (st < 7) MST_ISSUE(st + 1, (st + 1) & 1);
        if (st < 7) { CP_WAIT(1); } else { CP_WAIT(0); }
        __syncthreads();

#pragma unroll
        for (int half = 0; half < 2; half++) {
            const uint32_t* K32 =
                (const uint32_t*)((char*)sm + QHB + (st & 1)*QHB + half*(128*144));

            float c[4][8][4];
#pragma unroll
            for (int i = 0; i < 4; i++)
#pragma unroll
                for (int j = 0; j < 8; j++)
#pragma unroll
                    for (int r = 0; r < 4; r++) c[i][j][r] = 0.f;

#pragma unroll
            for (int kk = 0; kk < 4; kk++) {     // 4 k-steps of 16
                int kbs = kk * 8;
                uint32_t af[4][4];
#pragma unroll
                for (int mt = 0; mt < 4; mt++)
                    ldmA(af[mt], lmBase + (uint32_t)(mt*16*144 + kk*32));
                uint32_t bf[8][2];
#pragma unroll
                for (int nt2 = 0; nt2 < 8; nt2++) {
                    int base = (wn*64 + nt2*8 + g)*HPADW + kbs + tig;
                    bf[nt2][0] = K32[base];
                    bf[nt2][1] = K32[base + 4];
                }
#pragma unroll
                for (int mt = 0; mt < 4; mt++)
#pragma unroll
                    for (int nt2 = 0; nt2 < 8; nt2++)
                        mma_bf16(c[mt][nt2], af[mt], bf[nt2]);
            }

#pragma unroll
            for (int mt = 0; mt < 4; mt++)
#pragma unroll
                for (int nt2 = 0; nt2 < 8; nt2++) {
                    mx[mt*2+0]  = fmaxf(mx[mt*2+0], fmaxf(c[mt][nt2][0], c[mt][nt2][1]));
                    sum[mt*2+0] += c[mt][nt2][0] + c[mt][nt2][1];
                    mx[mt*2+1]  = fmaxf(mx[mt*2+1], fmaxf(c[mt][nt2][2], c[mt][nt2][3]));
                    sum[mt*2+1] += c[mt][nt2][2] + c[mt][nt2][3];
                }
        }
        __syncthreads();
    }
#undef MST_ISSUE

    // reduce over the 4 tig lanes sharing each row
#pragma unroll
    for (int s = 0; s < 8; s++) {
        mx[s]  = fmaxf(mx[s],  __shfl_xor_sync(0xffffffff, mx[s], 1));
        mx[s]  = fmaxf(mx[s],  __shfl_xor_sync(0xffffffff, mx[s], 2));
        sum[s] += __shfl_xor_sync(0xffffffff, sum[s], 1);
        sum[s] += __shfl_xor_sync(0xffffffff, sum[s], 2);
    }
    if (tig == 0) {
#pragma unroll
        for (int mt = 0; mt < 4; mt++)
#pragma unroll
            for (int hi = 0; hi < 2; hi++) {
                int row = wm*64 + mt*16 + g + hi*8;
                redm[wn*256 + row] = mx[mt*2+hi];
                reds[wn*256 + row] = sum[mt*2+hi];
            }
    }
    __syncthreads();
    {
        int row = t;
        float m = fmaxf(redm[row], redm[256 + row]);
        float s = reds[row] + reds[256 + row];
        g_M[(size_t)bh*LL + q0 + row] = SCALE * (m - s * (1.f/LL));
    }
}

// ---------------- parallel top-U: phase 1 per-256 chunk top-40 -------------
__global__ void topk_part() {
    int t = threadIdx.x;               // grid (8, 32), block 256
    int chunk = blockIdx.x, bh = blockIdx.y;
    int w = t >> 5, l = t & 31;
    __shared__ float rv[8];
    __shared__ int   ri[8];
    __shared__ int   besti;
    int myidx = chunk*256 + t;
    float v = g_M[(size_t)bh*LL + myidx];
    for (int u = 0; u < UU; u++) {
        float mv = v; int mi = myidx;
#pragma unroll
        for (int o = 16; o; o >>= 1) {
            float ov = __shfl_xor_sync(~0u, mv, o);
            int   oi = __shfl_xor_sync(~0u, mi, o);
            if (ov > mv || (ov == mv && oi < mi)) { mv = ov; mi = oi; }
        }
        if (l == 0) { rv[w] = mv; ri[w] = mi; }
        __syncthreads();
        if (t == 0) {
            float bv2 = rv[0]; int bi2 = ri[0];
#pragma unroll
            for (int i = 1; i < 8; i++)
                if (rv[i] > bv2 || (rv[i] == bv2 && ri[i] < bi2)) { bv2 = rv[i]; bi2 = ri[i]; }
            besti = bi2;
            g_cval[(bh*8 + chunk)*UU + u] = bv2;
            g_cidx[(bh*8 + chunk)*UU + u] = bi2;
        }
        __syncthreads();
        if (myidx == besti) v = -INFINITY;
    }
}

// ---------------- parallel top-U: phase 2 merge 320 candidates -------------
__global__ void topk_merge() {
    int t = threadIdx.x;               // grid 32, block 320
    int bh = blockIdx.x;
    int w = t >> 5, l = t & 31;
    __shared__ float rv[10];
    __shared__ int   ri[10];
    __shared__ int   besti;
    float v = g_cval[bh*8*UU + t];
    int   idx = g_cidx[bh*8*UU + t];
    for (int u = 0; u < UU; u++) {
        float mv = v; int mi = idx;
#pragma unroll
        for (int o = 16; o; o >>= 1) {
            float ov = __shfl_xor_sync(~0u, mv, o);
            int   oi = __shfl_xor_sync(~0u, mi, o);
            if (ov > mv || (ov == mv && oi < mi)) { mv = ov; mi = oi; }
        }
        if (l == 0) { rv[w] = mv; ri[w] = mi; }
        __syncthreads();
        if (t == 0) {
            float bv2 = rv[0]; int bi2 = ri[0];
#pragma unroll
            for (int i = 1; i < 10; i++)
                if (rv[i] > bv2 || (rv[i] == bv2 && ri[i] < bi2)) { bv2 = rv[i]; bi2 = ri[i]; }
            besti = bi2;
            g_topk[bh*UU + u] = bi2;
        }
        __syncthreads();
        if (idx == besti) v = -INFINITY;
    }
}

// =============== fused split-KV sparse attention ===========================
#define ATT_SMEM_FLOATS (2720 + 8704 + 8704 + 5280 + 120)
__global__ void __launch_bounds__(256, 2) attn_part() {
    extern __shared__ float sm[];
    float* Qs = sm;
    float* Ks = sm + 2720;
    float* Vs = sm + 11424;
    float* S  = sm + 20128;
    float* Mv = sm + 25408;
    float* Al = sm + 25448;
    float* Lv = sm + 25488;

    int t = threadIdx.x;
    int split = blockIdx.x, bh = blockIdx.y;
    int b = bh >> 3, h = bh & 7;
    int w = t >> 5, l = t & 31;
    int j = t & 127, qs = t >> 7;
    int d = t & 63,  qg = t >> 6;

    for (int idx = t; idx < 640; idx += 256) {
        int u = idx >> 4, c4 = (idx & 15) * 4;
        int lq = g_topk[bh*UU + u];
        *(float4*)&Qs[u*68 + c4] =
            *(const float4*)&g_q[((size_t)(b*LL + lq))*DD + h*DHH + c4];
    }
    if (t < 40) { Mv[t] = -INFINITY; Lv[t] = 0.f; }

    float acc[10];
#pragma unroll
    for (int i = 0; i < 10; i++) acc[i] = 0.f;
    float vsum = 0.f;

    for (int tt = 0; tt < ATILES; tt++) {
        int n0 = (split*ATILES + tt) * 128;
        __syncthreads();
#pragma unroll
        for (int r = 0; r < 8; r++) {
            int idx = r*256 + t;
            int row = idx >> 4, c4 = (idx & 15) * 4;
            size_t gofs = ((size_t)(b*LL + n0 + row))*DD + h*DHH + c4;
            *(float4*)&Ks[row*68 + c4] = *(const float4*)&g_k[gofs];
            *(float4*)&Vs[row*68 + c4] = *(const float4*)&g_v[gofs];
        }
        __syncthreads();

        // V column partial sums: all 256 threads, 32 rows each
#pragma unroll 8
        for (int jj = qg*32; jj < qg*32 + 32; jj++) vsum += Vs[jj*68 + d];

        float s[20];
#pragma unroll
        for (int i = 0; i < 20; i++) s[i] = 0.f;
#pragma unroll
        for (int d4 = 0; d4 < 16; d4++) {
            float4 kv = *(float4*)&Ks[j*68 + d4*4];
#pragma unroll
            for (int i = 0; i < 20; i++) {
                float4 qv = *(float4*)&Qs[(qs + 2*i)*68 + d4*4];
                s[i] += qv.x*kv.x + qv.y*kv.y + qv.z*kv.z + qv.w*kv.w;
            }
        }
#pragma unroll
        for (int i = 0; i < 20; i++) S[(qs + 2*i)*132 + j] = s[i] * SCALE;
        __syncthreads();

#pragma unroll
        for (int r = 0; r < 5; r++) {
            int q = w*5 + r;
            float mxv = fmaxf(fmaxf(S[q*132 + l], S[q*132 + l + 32]),
                              fmaxf(S[q*132 + l + 64], S[q*132 + l + 96]));
#pragma unroll
            for (int o = 16; o; o >>= 1) mxv = fmaxf(mxv, __shfl_xor_sync(~0u, mxv, o));
            if (l == 0) {
                float mn = fmaxf(Mv[q], mxv);
                Al[q] = __expf(Mv[q] - mn);
                Mv[q] = mn;
            }
        }
        __syncthreads();

#pragma unroll
        for (int i = 0; i < 20; i++) {
            int q = qs + 2*i;
            S[q*132 + j] = __expf(S[q*132 + j] - Mv[q]);
        }
        __syncthreads();

#pragma unroll
        for (int r = 0; r < 5; r++) {
            int q = w*5 + r;
            float sme = S[q*132 + l] + S[q*132 + l + 32]
                      + S[q*132 + l + 64] + S[q*132 + l + 96];
#pragma unroll
            for (int o = 16; o; o >>= 1) sme += __shfl_xor_sync(~0u, sme, o);
            if (l == 0) Lv[q] = Lv[q]*Al[q] + sme;
        }
#pragma unroll
        for (int i = 0; i < 10; i++) acc[i] *= Al[qg + 4*i];
        for (int jj = 0; jj < 128; jj += 4) {
            float v0 = Vs[(jj+0)*68 + d];
            float v1 = Vs[(jj+1)*68 + d];
            float v2 = Vs[(jj+2)*68 + d];
            float v3 = Vs[(jj+3)*68 + d];
#pragma unroll
            for (int i = 0; i < 10; i++) {
                float4 s4 = *(float4*)&S[(qg + 4*i)*132 + jj];
                acc[i] += s4.x*v0 + s4.y*v1 + s4.z*v2 + s4.w*v3;
            }
        }
    }
    __syncthreads();

    // cross-group vsum reduce via S (free now)
    S[qg*64 + d] = vsum;

    int base = bh*ASPLIT + split;
#pragma unroll
    for (int i = 0; i < 10; i++)
        g_pacc[((size_t)base*UU + qg + 4*i)*DHH + d] = acc[i];
    if (t < 40) { g_pm[base*UU + t] = Mv[t]; g_pl[base*UU + t] = Lv[t]; }
    __syncthreads();
    if (t < 64)
        g_pvs[base*DHH + t] = S[t] + S[64 + t] + S[128 + t] + S[192 + t];
}

// ---------------- ctx fill (V-mean broadcast, pvs summed inline) -----------
__global__ void ctx_fill_kernel() {
    int row = blockIdx.x;
    int d   = blockIdx.y*256 + threadIdx.x;
    int b   = row >> 11;
    int h = d >> 6, dh = d & 63;
    int bh = b*HH + h;
    float s = 0.f;
#pragma unroll
    for (int sp = 0; sp < ASPLIT; sp++) s += g_pvs[(bh*ASPLIT + sp)*DHH + dh];
    g_ctx[(size_t)row*DD + d] = s * (1.f/LL);
}

__global__ void attn_combine() {
    int t = threadIdx.x, bh = blockIdx.x;     // <<<32, 256>>>
    int b = bh >> 3, h = bh & 7;
    int d = t & 63, qg = t >> 6;
#pragma unroll
    for (int i = 0; i < 10; i++) {
        int q = qg + 4*i;
        float ms[ASPLIT], M = -INFINITY;
#pragma unroll
        for (int s = 0; s < ASPLIT; s++) {
            ms[s] = g_pm[(bh*ASPLIT + s)*UU + q];
            M = fmaxf(M, ms[s]);
        }
        float L = 0.f, o = 0.f;
#pragma unroll
        for (int s = 0; s < ASPLIT; s++) {
            float wv = __expf(ms[s] - M);
            L += g_pl[(bh*ASPLIT + s)*UU + q] * wv;
            o += g_pacc[((size_t)(bh*ASPLIT + s)*UU + q)*DHH + d] * wv;
        }
        int lq = g_topk[bh*UU + q];
        g_ctx[((size_t)(b*LL + lq))*DD + h*DHH + d] = o / L;
    }
}

// ---------------- residual + LayerNorm (single-pass sum/sumsq) -------------
__global__ void lnres_kernel(const float* __restrict__ delta,
                             const float* __restrict__ gam,
                             const float* __restrict__ bet) {
    int row = blockIdx.x;
    int t   = threadIdx.x, w = t >> 5, l = t & 31;
    __shared__ float ss[8], qq[8];
    float v0 = g_h[(size_t)row*DD + t]       + delta[(size_t)row*DD + t];
    float v1 = g_h[(size_t)row*DD + t + 256] + delta[(size_t)row*DD + t + 256];
    float s = v0 + v1;
    float q = v0*v0 + v1*v1;
#pragma unroll
    for (int o = 16; o; o >>= 1) {
        s += __shfl_xor_sync(~0u, s, o);
        q += __shfl_xor_sync(~0u, q, o);
    }
    if (l == 0) { ss[w] = s; qq[w] = q; }
    __syncthreads();
    float S = 0.f, Q = 0.f;
#pragma unroll
    for (int i = 0; i < 8; i++) { S += ss[i]; Q += qq[i]; }
    float mean = S * (1.f/DD);
    float var  = Q * (1.f/DD) - mean*mean;
    float inv = rsqrtf(var + 1e-5f);
    g_h[(size_t)row*DD + t]       = (v0 - mean)*inv*gam[t]     + bet[t];
    g_h[(size_t)row*DD + t + 256] = (v1 - mean)*inv*gam[t+256] + bet[t+256];
}

// ---------------- final projection -----------------------------------------
__global__ void proj_kernel(const float* __restrict__ w,
                            const float* __restrict__ b,
                            float* __restrict__ out) {
    int t  = threadIdx.x, wr = t >> 5, l = t & 31;
    int bp = blockIdx.x;
    int bb = bp / PP, p = bp % PP;
    int row = bb*LL + (LL - PP) + p;
    float acc[EE];
#pragma unroll
    for (int e = 0; e < EE; e++) acc[e] = 0.f;
    for (int d = t; d < DD; d += 256) {
        float hv = g_h[(size_t)row*DD + d];
#pragma unroll
        for (int e = 0; e < EE; e++) acc[e] += hv * w[d*EE + e];
    }
    __shared__ float red[8][EE];
#pragma unroll
    for (int e = 0; e < EE; e++) {
#pragma unroll
        for (int o = 16; o; o >>= 1) acc[e] += __shfl_xor_sync(~0u, acc[e], o);
        if (l == 0) red[wr][e] = acc[e];
    }
    __syncthreads();
    if (t < EE) {
        float s = 0.f;
#pragma unroll
        for (int i = 0; i < 8; i++) s += red[i][t];
        out[bp*EE + t] = s + b[t];
    }
}

// ---------------- host orchestration ---------------------------------------
extern "C" void kernel_launch(void* const* d_in, const int* in_sizes, int n_in,
                              void* d_out, int out_size) {
    const float* x      = (const float*)d_in[0];
    const float* emb_w  = (const float*)d_in[1];
    const float* emb_b  = (const float*)d_in[2];
    const float* Wq     = (const float*)d_in[3];
    const float* bq     = (const float*)d_in[4];
    const float* Wk     = (const float*)d_in[5];
    const float* bk     = (const float*)d_in[6];
    const float* Wv     = (const float*)d_in[7];
    const float* bv     = (const float*)d_in[8];
    const float* Wo     = (const float*)d_in[9];
    const float* bo     = (const float*)d_in[10];
    const float* W1     = (const float*)d_in[11];
    const float* b1     = (const float*)d_in[12];
    const float* W2     = (const float*)d_in[13];
    const float* b2     = (const float*)d_in[14];
    const float* ln1_g  = (const float*)d_in[15];
    const float* ln1_b  = (const float*)d_in[16];
    const float* ln2_g  = (const float*)d_in[17];
    const float* ln2_b  = (const float*)d_in[18];
    const float* proj_w = (const float*)d_in[19];
    const float* proj_b = (const float*)d_in[20];
    float* out = (float*)d_out;

    float *ph, *pctx, *pt1, *pt2, *pwt;
    cudaGetSymbolAddress((void**)&ph,   g_h);
    cudaGetSymbolAddress((void**)&pctx, g_ctx);
    cudaGetSymbolAddress((void**)&pt1,  g_t1);
    cudaGetSymbolAddress((void**)&pt2,  g_t2);
    cudaGetSymbolAddress((void**)&pwt,  g_wt);

    const int GEMM_SMEM   = GSTAGE*(ABUF + BBUF)*sizeof(float);   // 165888
    const int MSTATS_SMEM = 3*QHB + 1024*4;                       // 114688
    const int ATT_SMEM    = ATT_SMEM_FLOATS*sizeof(float);        // 102112
    cudaFuncSetAttribute(gemm_mma,   cudaFuncAttributeMaxDynamicSharedMemorySize, GEMM_SMEM);
    cudaFuncSetAttribute(gemm_qkv,   cudaFuncAttributeMaxDynamicSharedMemorySize, GEMM_SMEM);
    cudaFuncSetAttribute(mstats_mma, cudaFuncAttributeMaxDynamicSharedMemorySize, MSTATS_SMEM);
    cudaFuncSetAttribute(attn_part,  cudaFuncAttributeMaxDynamicSharedMemorySize, ATT_SMEM);

    transpose_all<<<dim3(16, 16, 12), dim3(32, 8)>>>(Wq, Wk, Wv, Wo, W1, W2);
    embed_kernel<<<dim3(BL, DD/256), 256>>>(x, emb_w, emb_b);

    dim3 ggrid(DD/128, BL/256);       // (4, 32)

    for (int lay = 0; lay < NLL; lay++) {
        float* tWo = pwt + (size_t)(lay*6 + 3)*DD*DD;
        float* tW1 = pwt + (size_t)(lay*6 + 4)*DD*DD;
        float* tW2 = pwt + (size_t)(lay*6 + 5)*DD*DD;

        gemm_qkv<<<dim3(DD/128, BL/256, 3), 256, GEMM_SMEM>>>(
            lay, bq + lay*DD, bk + lay*DD, bv + lay*DD);

        mstats_mma<<<dim3(LL/256, BB*HH), 256, MSTATS_SMEM>>>();
        topk_part<<<dim3(8, BB*HH), 256>>>();
        topk_merge<<<BB*HH, 320>>>();

        attn_part<<<dim3(ASPLIT, BB*HH), 256, ATT_SMEM>>>();
        ctx_fill_kernel<<<dim3(BL, DD/256), 256>>>();
        attn_combine<<<BB*HH, 256>>>();

        gemm_mma<<<ggrid, 256, GEMM_SMEM>>>(pctx, tWo, bo + lay*DD, pt1, 0);
        lnres_kernel<<<BL, 256>>>(pt1, ln1_g + lay*DD, ln1_b + lay*DD);

        gemm_mma<<<ggrid, 256, GEMM_SMEM>>>(ph, tW1, b1 + lay*DD, pt1, 1);
        gemm_mma<<<ggrid, 256, GEMM_SMEM>>>(pt1, tW2, b2 + lay*DD, pt2, 0);
        lnres_kernel<<<BL, 256>>>(pt2, ln2_g + lay*DD, ln2_b + lay*DD);
    }

    proj_kernel<<<BB*PP, 256>>>(proj_w, proj_b, out);
}